// round 2
// baseline (speedup 1.0000x reference)
#include <cuda_runtime.h>
#include <cuda_bf16.h>
#include <math.h>

#define NUM_CLASSES 19
#define KPC 100
#define NA 1900
#define NA_PAD 1920
#define NMEM 20000
#define NCOLS 21900
#define NC_PAD 21952
#define DIMS 256
#define HW 16384
#define NLAB 131072
#define LBLK 1024
#define NLBLK 128
#define ROW_TILES 15
#define COL_CHUNKS 20
#define NSUB 343
#define TEMP_INV 10.0f
#define LOSS_SCALE 1.4285714285714286f

// -------------------- device scratch (no allocations allowed) --------------------
__device__ int g_lab64;                       // 1 if labels are int64, 0 if int32
__device__ int g_bcnt[NLBLK * NUM_CLASSES];
__device__ int g_boff[NLBLK * NUM_CLASSES];
__device__ int g_idx[NA];
__device__ __align__(16) __nv_bfloat16 g_A[NA_PAD * DIMS];   // normalized anchors (bf16)
__device__ __align__(16) __nv_bfloat16 g_C[NC_PAD * DIMS];   // normalized contrast (bf16)
__device__ int g_clab[NC_PAD];
__device__ float g_Sp[NA_PAD * COL_CHUNKS];
__device__ float g_Pp[NA_PAD * COL_CHUNKS];

__device__ __forceinline__ int load_label(const void* p, int i) {
    if (g_lab64) return (int)((const long long*)p)[i];
    return ((const int*)p)[i];
}

// fast exp on the FMA pipe (no MUFU, no F2I): rel err ~1e-7 for |x| <= ~20
__device__ __forceinline__ float fexp(float x) {
    float z  = x * 1.4426950408889634f;
    float zf = z + 12582912.0f;                 // round-to-nearest int in mantissa
    int   zi = __float_as_int(zf);
    float n  = zf - 12582912.0f;
    float f  = z - n;                           // f in [-0.5, 0.5]
    float p  = 1.5403530393381609e-4f;
    p = fmaf(p, f, 1.3333558146428443e-3f);
    p = fmaf(p, f, 9.6181291076284772e-3f);
    p = fmaf(p, f, 5.5504108664821580e-2f);
    p = fmaf(p, f, 2.4022650695910071e-1f);
    p = fmaf(p, f, 6.9314718055994531e-1f);
    p = fmaf(p, f, 1.0f);
    float s = __int_as_float((zi << 23) + 0x3F800000);  // 2^n (wraps correctly for n<0)
    return p * s;
}

__device__ __forceinline__ void mma_bf16(float* d, const unsigned* a, const unsigned* b) {
    asm volatile(
        "mma.sync.aligned.m16n8k16.row.col.f32.bf16.bf16.f32 "
        "{%0,%1,%2,%3}, {%4,%5,%6,%7}, {%8,%9}, {%0,%1,%2,%3};\n"
        : "+f"(d[0]), "+f"(d[1]), "+f"(d[2]), "+f"(d[3])
        : "r"(a[0]), "r"(a[1]), "r"(a[2]), "r"(a[3]), "r"(b[0]), "r"(b[1]));
}

// -------------------- label dtype detection --------------------
__global__ void k_detect(const int* lab32) {
    if (threadIdx.x == 0 && blockIdx.x == 0) {
        int is64 = 1;
        #pragma unroll 1
        for (int i = 1; i < 2048; i += 2) {
            if (lab32[i] != 0) { is64 = 0; break; }
        }
        g_lab64 = is64;
    }
}

// -------------------- sampling: per-block class histogram --------------------
__global__ void k_count(const void* labels) {
    __shared__ int scnt[NUM_CLASSES];
    int t = threadIdx.x;
    if (t < NUM_CLASSES) scnt[t] = 0;
    __syncthreads();
    int base = blockIdx.x * LBLK;
    for (int i = t; i < LBLK; i += 256) {
        int c = load_label(labels, base + i);
        atomicAdd(&scnt[c], 1);
    }
    __syncthreads();
    if (t < NUM_CLASSES) g_bcnt[blockIdx.x * NUM_CLASSES + t] = scnt[t];
}

__global__ void k_scan() {
    int c = threadIdx.x;
    if (c >= NUM_CLASSES) return;
    int run = 0;
    for (int b = 0; b < NLBLK; b++) {
        g_boff[b * NUM_CLASSES + c] = run;
        run += g_bcnt[b * NUM_CLASSES + c];
    }
}

__global__ void k_select(const void* labels) {
    __shared__ int slab[LBLK];
    int t = threadIdx.x;
    int base = blockIdx.x * LBLK;
    for (int i = t; i < LBLK; i += 256)
        slab[i] = load_label(labels, base + i);
    __syncthreads();
    if (t < NUM_CLASSES) {
        int r = g_boff[blockIdx.x * NUM_CLASSES + t];
        #pragma unroll 4
        for (int i = 0; i < LBLK; i++) {
            if (slab[i] == t) {
                if (r < KPC) g_idx[t * KPC + r] = base + i;
                r++;
            }
        }
    }
}

// -------------------- gather + normalize anchors (warp per row) --------------------
__global__ void k_anchor(const float* __restrict__ pf) {
    int wid  = threadIdx.x >> 5;
    int lane = threadIdx.x & 31;
    int n = blockIdx.x * 8 + wid;          // grid = 240 -> n in [0,1920)
    float v[8];
    if (n < NA) {
        int idx = g_idx[n];
        int b   = idx >> 14;               // / HW
        int rem = idx & (HW - 1);
        const float* src = pf + (size_t)b * (DIMS * HW) + rem;
        #pragma unroll
        for (int j = 0; j < 8; j++)
            v[j] = src[(size_t)(lane + 32 * j) * HW];
    } else {
        #pragma unroll
        for (int j = 0; j < 8; j++) v[j] = 0.f;
    }
    float ss = 0.f;
    #pragma unroll
    for (int j = 0; j < 8; j++) ss += v[j] * v[j];
    #pragma unroll
    for (int o = 16; o; o >>= 1) ss += __shfl_xor_sync(0xffffffffu, ss, o);
    float sc = (n < NA) ? (1.f / fmaxf(sqrtf(ss), 1e-12f)) : 0.f;
    #pragma unroll
    for (int j = 0; j < 8; j++) {
        __nv_bfloat16 o16 = __float2bfloat16(v[j] * sc);
        int d = lane + 32 * j;
        g_A[n * DIMS + d] = o16;
        g_C[n * DIMS + d] = o16;
    }
}

// -------------------- normalize memory feats (warp per row) --------------------
__global__ void k_mem(const float* __restrict__ mf) {
    int wid  = threadIdx.x >> 5;
    int lane = threadIdx.x & 31;
    int m = blockIdx.x * 8 + wid;
    if (m >= NC_PAD - NA) return;          // 20052 rows (incl. zero pad)
    float v[8];
    if (m < NMEM) {
        const float* src = mf + (size_t)m * DIMS;
        #pragma unroll
        for (int j = 0; j < 8; j++) v[j] = src[lane + 32 * j];
    } else {
        #pragma unroll
        for (int j = 0; j < 8; j++) v[j] = 0.f;
    }
    float ss = 0.f;
    #pragma unroll
    for (int j = 0; j < 8; j++) ss += v[j] * v[j];
    #pragma unroll
    for (int o = 16; o; o >>= 1) ss += __shfl_xor_sync(0xffffffffu, ss, o);
    float sc = (m < NMEM) ? (1.f / fmaxf(sqrtf(ss), 1e-12f)) : 0.f;
    #pragma unroll
    for (int j = 0; j < 8; j++)
        g_C[(size_t)(NA + m) * DIMS + lane + 32 * j] = __float2bfloat16(v[j] * sc);
}

// -------------------- contrast labels --------------------
__global__ void k_label(const void* mlab) {
    int i = blockIdx.x * 256 + threadIdx.x;
    if (i >= NC_PAD) return;
    int v;
    if (i < NA)        v = i / KPC;
    else if (i < NCOLS) v = load_label(mlab, i - NA);
    else               v = -1;
    g_clab[i] = v;
}

// -------------------- fused GEMM + exp/softmax-denominator + positive-logit sums --------
// grid (COL_CHUNKS, ROW_TILES), 256 threads, dyn smem. Block tile: 128 rows x 64 cols,
// K = 256. 8 warps in 4x2 arrangement, 32x32 per warp via m16n8k16 bf16 MMA.
extern __shared__ char smem_raw[];

#define AS_BYTES (128 * 264 * 2)
#define CS_BYTES (64 * 264 * 2)
#define SMEM_BYTES (AS_BYTES + CS_BYTES + 64 * 4 + 2 * 256 * 4)

__global__ void __launch_bounds__(256) k_main() {
    __nv_bfloat16* As = (__nv_bfloat16*)smem_raw;                        // [128][264]
    __nv_bfloat16* Cs = (__nv_bfloat16*)(smem_raw + AS_BYTES);           // [64][264]
    int*   clab_sm = (int*)(smem_raw + AS_BYTES + CS_BYTES);             // [64]
    float* redS    = (float*)(smem_raw + AS_BYTES + CS_BYTES + 64 * 4);  // [128][2]
    float* redP    = redS + 256;

    const int tid     = threadIdx.x;
    const int chunk   = blockIdx.x;
    const int rowbase = blockIdx.y * 128;
    const int lane = tid & 31;
    const int w    = tid >> 5;
    const int wr   = w >> 1;       // 0..3
    const int wc   = w & 1;        // 0..1
    const int g    = lane >> 2;    // groupID 0..7
    const int t2   = (lane & 3) * 2;

    // Load A tile [128][256]: 128 rows x 32 uint4-chunks = 4096 loads
    #pragma unroll
    for (int it = 0; it < 16; it++) {
        int lin = tid + it * 256;
        int row = lin >> 5;          // 0..127
        int kv  = lin & 31;          // 0..31 (8 bf16 each)
        *(uint4*)(As + row * 264 + kv * 8) =
            *(const uint4*)(g_A + (size_t)(rowbase + row) * DIMS + kv * 8);
    }

    float Sacc[2][2] = {{0.f, 0.f}, {0.f, 0.f}};
    float Pacc[2][2] = {{0.f, 0.f}, {0.f, 0.f}};
    int rlab[2][2], grow[2][2];
    #pragma unroll
    for (int mb = 0; mb < 2; mb++)
        #pragma unroll
        for (int p = 0; p < 2; p++) {
            int r = rowbase + wr * 32 + mb * 16 + g + 8 * p;
            grow[mb][p] = r;
            rlab[mb][p] = (r < NA) ? (r / KPC) : -2;
        }

    for (int s = chunk; s < NSUB; s += COL_CHUNKS) {
        const int colbase = s * 64;
        __syncthreads();   // prior iter's Cs/clab consumers done (covers A load on iter 1)
        #pragma unroll
        for (int it = 0; it < 8; it++) {
            int lin = tid + it * 256;
            int row = lin >> 5;      // 0..63
            int kv  = lin & 31;      // 0..31
            *(uint4*)(Cs + row * 264 + kv * 8) =
                *(const uint4*)(g_C + (size_t)(colbase + row) * DIMS + kv * 8);
        }
        if (tid < 64) clab_sm[tid] = g_clab[colbase + tid];
        __syncthreads();

        float acc[2][4][4];
        #pragma unroll
        for (int mb = 0; mb < 2; mb++)
            #pragma unroll
            for (int nb = 0; nb < 4; nb++)
                #pragma unroll
                for (int i = 0; i < 4; i++) acc[mb][nb][i] = 0.f;

        #pragma unroll
        for (int k = 0; k < DIMS; k += 16) {
            unsigned a[2][4], b[4][2];
            #pragma unroll
            for (int mb = 0; mb < 2; mb++) {
                const __nv_bfloat16* a0 = As + (wr * 32 + mb * 16 + g) * 264 + k + t2;
                a[mb][0] = *(const unsigned*)(a0);
                a[mb][1] = *(const unsigned*)(a0 + 8 * 264);
                a[mb][2] = *(const unsigned*)(a0 + 8);
                a[mb][3] = *(const unsigned*)(a0 + 8 * 264 + 8);
            }
            #pragma unroll
            for (int nb = 0; nb < 4; nb++) {
                const __nv_bfloat16* cb = Cs + (wc * 32 + nb * 8 + g) * 264 + k + t2;
                b[nb][0] = *(const unsigned*)(cb);
                b[nb][1] = *(const unsigned*)(cb + 8);
            }
            #pragma unroll
            for (int mb = 0; mb < 2; mb++)
                #pragma unroll
                for (int nb = 0; nb < 4; nb++)
                    mma_bf16(acc[mb][nb], a[mb], b[nb]);
        }

        // register epilogue: scale, mask self + padding, exp-sum & positive-logit-sum
        #pragma unroll
        for (int mb = 0; mb < 2; mb++)
            #pragma unroll
            for (int nb = 0; nb < 4; nb++) {
                int colb = wc * 32 + nb * 8 + t2;
                #pragma unroll
                for (int p = 0; p < 2; p++)
                    #pragma unroll
                    for (int e = 0; e < 2; e++) {
                        float l = acc[mb][nb][2 * p + e] * TEMP_INV;
                        int col  = colb + e;
                        int gcol = colbase + col;
                        if (gcol < NCOLS && gcol != grow[mb][p]) {
                            Sacc[mb][p] += fexp(l);
                            if (clab_sm[col] == rlab[mb][p]) Pacc[mb][p] += l;
                        }
                    }
            }
    }

    // reduce across the 4 lanes of each group (lane bits 0,1), then across warp cols
    #pragma unroll
    for (int mb = 0; mb < 2; mb++)
        #pragma unroll
        for (int p = 0; p < 2; p++) {
            float sv = Sacc[mb][p], pv = Pacc[mb][p];
            sv += __shfl_xor_sync(0xffffffffu, sv, 1);
            sv += __shfl_xor_sync(0xffffffffu, sv, 2);
            pv += __shfl_xor_sync(0xffffffffu, pv, 1);
            pv += __shfl_xor_sync(0xffffffffu, pv, 2);
            if ((lane & 3) == 0) {
                int row = wr * 32 + mb * 16 + g + 8 * p;
                redS[row * 2 + wc] = sv;
                redP[row * 2 + wc] = pv;
            }
        }
    __syncthreads();
    if (tid < 128) {
        int r = rowbase + tid;
        g_Sp[r * COL_CHUNKS + chunk] = redS[tid * 2] + redS[tid * 2 + 1];
        g_Pp[r * COL_CHUNKS + chunk] = redP[tid * 2] + redP[tid * 2 + 1];
    }
}

// -------------------- final scalar reduction --------------------
__global__ void k_final(const void* mlab, float* out) {
    __shared__ int scnt[NUM_CLASSES];
    __shared__ float ssum[256];
    int t = threadIdx.x;
    if (t < NUM_CLASSES) scnt[t] = 0;
    __syncthreads();
    for (int i = t; i < NMEM; i += 256)
        atomicAdd(&scnt[load_label(mlab, i)], 1);
    __syncthreads();
    float local = 0.f;
    for (int n = t; n < NA; n += 256) {
        float S = 0.f, P = 0.f;
        #pragma unroll
        for (int ch = 0; ch < COL_CHUNKS; ch++) {
            S += g_Sp[n * COL_CHUNKS + ch];
            P += g_Pp[n * COL_CHUNKS + ch];
        }
        float cnt = (float)(KPC - 1 + scnt[n / KPC]);
        local += (P - cnt * logf(S + 1e-12f)) / cnt;
    }
    ssum[t] = local;
    __syncthreads();
    for (int off = 128; off; off >>= 1) {
        if (t < off) ssum[t] += ssum[t + off];
        __syncthreads();
    }
    if (t == 0) out[0] = -LOSS_SCALE * ssum[0] / (float)NA;
}

// -------------------- launch --------------------
extern "C" void kernel_launch(void* const* d_in, const int* in_sizes, int n_in,
                              void* d_out, int out_size) {
    (void)in_sizes; (void)n_in; (void)out_size;
    const float* pf  = (const float*)d_in[0];
    const void*  lab = d_in[1];
    const float* mf  = (const float*)d_in[2];
    const void*  mlab = d_in[3];
    float* out = (float*)d_out;

    cudaFuncSetAttribute(k_main, cudaFuncAttributeMaxDynamicSharedMemorySize, SMEM_BYTES);

    k_detect<<<1, 1>>>((const int*)lab);
    k_count<<<NLBLK, 256>>>(lab);
    k_scan<<<1, 32>>>();
    k_select<<<NLBLK, 256>>>(lab);
    k_anchor<<<NA_PAD / 8, 256>>>(pf);
    k_mem<<<(NC_PAD - NA + 7) / 8, 256>>>(mf);
    k_label<<<(NC_PAD + 255) / 256, 256>>>(mlab);
    k_main<<<dim3(COL_CHUNKS, ROW_TILES), 256, SMEM_BYTES>>>();
    k_final<<<1, 256>>>(mlab, out);
}

// round 3
// speedup vs baseline: 1.1331x; 1.1331x over previous
#include <cuda_runtime.h>
#include <cuda_bf16.h>
#include <math.h>

#define NUM_CLASSES 19
#define KPC 100
#define NA 1900
#define NA_PAD 1920
#define NMEM 20000
#define NCOLS 21900
#define NC_PAD 21952
#define DIMS 256
#define HW 16384
#define LBLK 1024
#define NLBLK 128
#define ROW_TILES 15
#define COL_CHUNKS 20
#define NSUB 343
#define TEMP_INV 10.0f
#define L2E10 14.426950408889634f
#define LOSS_SCALE 1.4285714285714286f

// -------------------- device scratch --------------------
__device__ int g_lab64;
__device__ int g_bcnt[NLBLK * NUM_CLASSES];
__device__ int g_boff[NLBLK * NUM_CLASSES];
__device__ int g_idx[NA];
__device__ __align__(16) __nv_bfloat16 g_A[NA_PAD * DIMS];
__device__ __align__(16) __nv_bfloat16 g_C[NC_PAD * DIMS];
__device__ int g_clab[NC_PAD];
__device__ float g_Sp[NA_PAD * COL_CHUNKS];
__device__ float g_Pp[NA_PAD * COL_CHUNKS];

__device__ __forceinline__ int load_label(const void* p, int i) {
    if (g_lab64) return (int)((const long long*)p)[i];
    return ((const int*)p)[i];
}

// fused exp-and-accumulate: S += exp(10*acc), P += acc if labels match.
// exp on the FMA pipe only: zf=fma round trick + degree-6 2^f poly + exponent splice.
__device__ __forceinline__ void ep_core(float acc_v, int labv, int rl, float& S, float& P) {
    float zf = fmaf(acc_v, L2E10, 12582912.0f);     // rint(acc*10*log2e) in mantissa
    int   zi = __float_as_int(zf);
    float n  = zf - 12582912.0f;
    float f  = fmaf(acc_v, L2E10, -n);              // frac in [-0.5, 0.5]
    float p  = 1.5403530393381609e-4f;
    p = fmaf(p, f, 1.3333558146428443e-3f);
    p = fmaf(p, f, 9.6181291076284772e-3f);
    p = fmaf(p, f, 5.5504108664821580e-2f);
    p = fmaf(p, f, 2.4022650695910071e-1f);
    p = fmaf(p, f, 6.9314718055994531e-1f);
    p = fmaf(p, f, 1.0f);
    float sc = __int_as_float((zi << 23) + 0x3F800000);
    S = fmaf(p, sc, S);
    if (labv == rl) P += acc_v;                     // raw dot; *10 in k_final
}

__device__ __forceinline__ void mma_bf16(float* d, const unsigned* a, const unsigned* b) {
    asm volatile(
        "mma.sync.aligned.m16n8k16.row.col.f32.bf16.bf16.f32 "
        "{%0,%1,%2,%3}, {%4,%5,%6,%7}, {%8,%9}, {%0,%1,%2,%3};\n"
        : "+f"(d[0]), "+f"(d[1]), "+f"(d[2]), "+f"(d[3])
        : "r"(a[0]), "r"(a[1]), "r"(a[2]), "r"(a[3]), "r"(b[0]), "r"(b[1]));
}

// -------------------- label dtype detection (parallel warp) --------------------
__global__ void k_detect(const int* lab32) {
    int lane = threadIdx.x;
    int bad = 0;
    #pragma unroll 4
    for (int i = lane; i < 1024; i += 32) bad |= lab32[2 * i + 1];
    unsigned m = __ballot_sync(0xffffffffu, bad != 0);
    if (lane == 0) g_lab64 = (m == 0) ? 1 : 0;
}

// -------------------- sampling --------------------
__global__ void k_count(const void* labels) {
    __shared__ int scnt[NUM_CLASSES];
    int t = threadIdx.x;
    if (t < NUM_CLASSES) scnt[t] = 0;
    __syncthreads();
    int base = blockIdx.x * LBLK;
    for (int i = t; i < LBLK; i += 256) {
        int c = load_label(labels, base + i);
        atomicAdd(&scnt[c], 1);
    }
    __syncthreads();
    if (t < NUM_CLASSES) g_bcnt[blockIdx.x * NUM_CLASSES + t] = scnt[t];
}

__global__ void k_scan() {
    int c = threadIdx.x;
    if (c >= NUM_CLASSES) return;
    int run = 0;
    for (int b = 0; b < NLBLK; b++) {
        g_boff[b * NUM_CLASSES + c] = run;
        run += g_bcnt[b * NUM_CLASSES + c];
    }
}

__global__ void k_select(const void* labels) {
    __shared__ int slab[LBLK];
    __shared__ int sactive;
    int t = threadIdx.x;
    int b = blockIdx.x;
    if (t == 0) sactive = 0;
    __syncthreads();
    if (t < NUM_CLASSES && g_boff[b * NUM_CLASSES + t] < KPC) sactive = 1;
    __syncthreads();
    if (!sactive) return;                         // ~125 of 128 blocks exit here
    int base = b * LBLK;
    for (int i = t; i < LBLK; i += 256)
        slab[i] = load_label(labels, base + i);
    __syncthreads();
    if (t < NUM_CLASSES) {
        int r = g_boff[b * NUM_CLASSES + t];
        if (r < KPC) {
            #pragma unroll 4
            for (int i = 0; i < LBLK; i++) {
                if (r >= KPC) break;
                if (slab[i] == t) { g_idx[t * KPC + r] = base + i; r++; }
            }
        }
    }
}

// -------------------- gather + normalize anchors --------------------
__global__ void k_anchor(const float* __restrict__ pf) {
    int wid  = threadIdx.x >> 5;
    int lane = threadIdx.x & 31;
    int n = blockIdx.x * 8 + wid;
    float v[8];
    if (n < NA) {
        int idx = g_idx[n];
        int b   = idx >> 14;
        int rem = idx & (HW - 1);
        const float* src = pf + (size_t)b * (DIMS * HW) + rem;
        #pragma unroll
        for (int j = 0; j < 8; j++)
            v[j] = src[(size_t)(lane + 32 * j) * HW];
    } else {
        #pragma unroll
        for (int j = 0; j < 8; j++) v[j] = 0.f;
    }
    float ss = 0.f;
    #pragma unroll
    for (int j = 0; j < 8; j++) ss += v[j] * v[j];
    #pragma unroll
    for (int o = 16; o; o >>= 1) ss += __shfl_xor_sync(0xffffffffu, ss, o);
    float sc = (n < NA) ? (1.f / fmaxf(sqrtf(ss), 1e-12f)) : 0.f;
    #pragma unroll
    for (int j = 0; j < 8; j++) {
        __nv_bfloat16 o16 = __float2bfloat16(v[j] * sc);
        int d = lane + 32 * j;
        g_A[n * DIMS + d] = o16;
        g_C[n * DIMS + d] = o16;
    }
}

// -------------------- normalize memory feats --------------------
__global__ void k_mem(const float* __restrict__ mf) {
    int wid  = threadIdx.x >> 5;
    int lane = threadIdx.x & 31;
    int m = blockIdx.x * 8 + wid;
    if (m >= NC_PAD - NA) return;
    float v[8];
    if (m < NMEM) {
        const float* src = mf + (size_t)m * DIMS;
        #pragma unroll
        for (int j = 0; j < 8; j++) v[j] = src[lane + 32 * j];
    } else {
        #pragma unroll
        for (int j = 0; j < 8; j++) v[j] = 0.f;
    }
    float ss = 0.f;
    #pragma unroll
    for (int j = 0; j < 8; j++) ss += v[j] * v[j];
    #pragma unroll
    for (int o = 16; o; o >>= 1) ss += __shfl_xor_sync(0xffffffffu, ss, o);
    float sc = (m < NMEM) ? (1.f / fmaxf(sqrtf(ss), 1e-12f)) : 0.f;
    #pragma unroll
    for (int j = 0; j < 8; j++)
        g_C[(size_t)(NA + m) * DIMS + lane + 32 * j] = __float2bfloat16(v[j] * sc);
}

__global__ void k_label(const void* mlab) {
    int i = blockIdx.x * 256 + threadIdx.x;
    if (i >= NC_PAD) return;
    int v;
    if (i < NA)         v = i / KPC;
    else if (i < NCOLS) v = load_label(mlab, i - NA);
    else                v = -1;
    g_clab[i] = v;
}

// -------------------- fused GEMM + softmax reductions --------------------
extern __shared__ char smem_raw[];

#define AS_BYTES (128 * 264 * 2)
#define CS_BYTES (64 * 264 * 2)
#define SMEM_BYTES (AS_BYTES + CS_BYTES + 64 * 4 + 2 * 256 * 4)

__global__ void __launch_bounds__(256) k_main() {
    __nv_bfloat16* As = (__nv_bfloat16*)smem_raw;                        // [128][264]
    __nv_bfloat16* Cs = (__nv_bfloat16*)(smem_raw + AS_BYTES);           // [64][264]
    int*   clab_sm = (int*)(smem_raw + AS_BYTES + CS_BYTES);             // [64]
    float* redS    = (float*)(smem_raw + AS_BYTES + CS_BYTES + 64 * 4);  // [128][2]
    float* redP    = redS + 256;

    const int tid     = threadIdx.x;
    const int chunk   = blockIdx.x;
    const int rowbase = blockIdx.y * 128;
    const int lane = tid & 31;
    const int w    = tid >> 5;
    const int wr   = w >> 1;
    const int wc   = w & 1;
    const int g    = lane >> 2;
    const int t2   = (lane & 3) * 2;

    // A tile [128][256]: 128 rows x 32 uint4 chunks
    #pragma unroll
    for (int it = 0; it < 16; it++) {
        int lin = tid + it * 256;
        int row = lin >> 5;
        int kv  = lin & 31;
        *(uint4*)(As + row * 264 + kv * 8) =
            *(const uint4*)(g_A + (size_t)(rowbase + row) * DIMS + kv * 8);
    }

    float Sacc[2][2] = {{0.f, 0.f}, {0.f, 0.f}};
    float Pacc[2][2] = {{0.f, 0.f}, {0.f, 0.f}};
    int rlab[2][2], grow[2][2];
    #pragma unroll
    for (int mb = 0; mb < 2; mb++)
        #pragma unroll
        for (int p = 0; p < 2; p++) {
            int r = rowbase + wr * 32 + mb * 16 + g + 8 * p;
            grow[mb][p] = r;
            rlab[mb][p] = (r < NA) ? (r / KPC) : -2;
        }

    for (int s = chunk; s < NSUB; s += COL_CHUNKS) {
        const int colbase = s * 64;
        const bool edge = (colbase + 64 > NCOLS) ||
                          ((colbase < rowbase + 128) && (colbase + 64 > rowbase));
        __syncthreads();
        #pragma unroll
        for (int it = 0; it < 8; it++) {
            int lin = tid + it * 256;
            int row = lin >> 5;
            int kv  = lin & 31;
            *(uint4*)(Cs + row * 264 + kv * 8) =
                *(const uint4*)(g_C + (size_t)(colbase + row) * DIMS + kv * 8);
        }
        if (tid < 64) clab_sm[tid] = g_clab[colbase + tid];
        __syncthreads();

        float acc[2][4][4];
        #pragma unroll
        for (int mb = 0; mb < 2; mb++)
            #pragma unroll
            for (int nb = 0; nb < 4; nb++)
                #pragma unroll
                for (int i = 0; i < 4; i++) acc[mb][nb][i] = 0.f;

        #pragma unroll
        for (int k = 0; k < DIMS; k += 16) {
            unsigned a[2][4], b[4][2];
            #pragma unroll
            for (int mb = 0; mb < 2; mb++) {
                const __nv_bfloat16* a0 = As + (wr * 32 + mb * 16 + g) * 264 + k + t2;
                a[mb][0] = *(const unsigned*)(a0);
                a[mb][1] = *(const unsigned*)(a0 + 8 * 264);
                a[mb][2] = *(const unsigned*)(a0 + 8);
                a[mb][3] = *(const unsigned*)(a0 + 8 * 264 + 8);
            }
            #pragma unroll
            for (int nb = 0; nb < 4; nb++) {
                const __nv_bfloat16* cb = Cs + (wc * 32 + nb * 8 + g) * 264 + k + t2;
                b[nb][0] = *(const unsigned*)(cb);
                b[nb][1] = *(const unsigned*)(cb + 8);
            }
            #pragma unroll
            for (int mb = 0; mb < 2; mb++)
                #pragma unroll
                for (int nb = 0; nb < 4; nb++)
                    mma_bf16(acc[mb][nb], a[mb], b[nb]);
        }

        // hoist this thread's 8 column labels (reused across mb,p)
        int labreg[8];
        #pragma unroll
        for (int nb = 0; nb < 4; nb++)
            #pragma unroll
            for (int e = 0; e < 2; e++)
                labreg[nb * 2 + e] = clab_sm[wc * 32 + nb * 8 + t2 + e];

        if (!edge) {
            #pragma unroll
            for (int mb = 0; mb < 2; mb++)
                #pragma unroll
                for (int nb = 0; nb < 4; nb++)
                    #pragma unroll
                    for (int p = 0; p < 2; p++)
                        #pragma unroll
                        for (int e = 0; e < 2; e++)
                            ep_core(acc[mb][nb][2 * p + e], labreg[nb * 2 + e],
                                    rlab[mb][p], Sacc[mb][p], Pacc[mb][p]);
        } else {
            #pragma unroll
            for (int mb = 0; mb < 2; mb++)
                #pragma unroll
                for (int nb = 0; nb < 4; nb++) {
                    int colb = wc * 32 + nb * 8 + t2;
                    #pragma unroll
                    for (int p = 0; p < 2; p++)
                        #pragma unroll
                        for (int e = 0; e < 2; e++) {
                            int gcol = colbase + colb + e;
                            if (gcol < NCOLS && gcol != grow[mb][p])
                                ep_core(acc[mb][nb][2 * p + e], labreg[nb * 2 + e],
                                        rlab[mb][p], Sacc[mb][p], Pacc[mb][p]);
                        }
                }
        }
    }

    #pragma unroll
    for (int mb = 0; mb < 2; mb++)
        #pragma unroll
        for (int p = 0; p < 2; p++) {
            float sv = Sacc[mb][p], pv = Pacc[mb][p];
            sv += __shfl_xor_sync(0xffffffffu, sv, 1);
            sv += __shfl_xor_sync(0xffffffffu, sv, 2);
            pv += __shfl_xor_sync(0xffffffffu, pv, 1);
            pv += __shfl_xor_sync(0xffffffffu, pv, 2);
            if ((lane & 3) == 0) {
                int row = wr * 32 + mb * 16 + g + 8 * p;
                redS[row * 2 + wc] = sv;
                redP[row * 2 + wc] = pv;
            }
        }
    __syncthreads();
    if (tid < 128) {
        int r = rowbase + tid;
        g_Sp[r * COL_CHUNKS + chunk] = redS[tid * 2] + redS[tid * 2 + 1];
        g_Pp[r * COL_CHUNKS + chunk] = redP[tid * 2] + redP[tid * 2 + 1];
    }
}

// -------------------- final scalar reduction --------------------
__global__ void k_final(const void* mlab, float* out) {
    __shared__ int scnt[NUM_CLASSES];
    __shared__ float ssum[256];
    int t = threadIdx.x;
    if (t < NUM_CLASSES) scnt[t] = 0;
    __syncthreads();
    for (int i = t; i < NMEM; i += 256)
        atomicAdd(&scnt[load_label(mlab, i)], 1);
    __syncthreads();
    float local = 0.f;
    for (int n = t; n < NA; n += 256) {
        float S = 0.f, P = 0.f;
        #pragma unroll
        for (int ch = 0; ch < COL_CHUNKS; ch++) {
            S += g_Sp[n * COL_CHUNKS + ch];
            P += g_Pp[n * COL_CHUNKS + ch];
        }
        float cnt = (float)(KPC - 1 + scnt[n / KPC]);
        local += (TEMP_INV * P - cnt * logf(S + 1e-12f)) / cnt;
    }
    ssum[t] = local;
    __syncthreads();
    for (int off = 128; off; off >>= 1) {
        if (t < off) ssum[t] += ssum[t + off];
        __syncthreads();
    }
    if (t == 0) out[0] = -LOSS_SCALE * ssum[0] / (float)NA;
}

// -------------------- launch --------------------
extern "C" void kernel_launch(void* const* d_in, const int* in_sizes, int n_in,
                              void* d_out, int out_size) {
    (void)in_sizes; (void)n_in; (void)out_size;
    const float* pf   = (const float*)d_in[0];
    const void*  lab  = d_in[1];
    const float* mf   = (const float*)d_in[2];
    const void*  mlab = d_in[3];
    float* out = (float*)d_out;

    cudaFuncSetAttribute(k_main, cudaFuncAttributeMaxDynamicSharedMemorySize, SMEM_BYTES);

    k_detect<<<1, 32>>>((const int*)lab);
    k_count<<<NLBLK, 256>>>(lab);
    k_scan<<<1, 32>>>();
    k_select<<<NLBLK, 256>>>(lab);
    k_anchor<<<NA_PAD / 8, 256>>>(pf);
    k_mem<<<(NC_PAD - NA + 7) / 8, 256>>>(mf);
    k_label<<<(NC_PAD + 255) / 256, 256>>>(mlab);
    k_main<<<dim3(COL_CHUNKS, ROW_TILES), 256, SMEM_BYTES>>>();
    k_final<<<1, 256>>>(mlab, out);
}

// round 4
// speedup vs baseline: 1.3399x; 1.1825x over previous
#include <cuda_runtime.h>
#include <cuda_bf16.h>
#include <math.h>

#define NUM_CLASSES 19
#define KPC 100
#define NA 1900
#define NA_PAD 1920
#define NMEM 20000
#define NCOLS 21900
#define NC_PAD 21952
#define DIMS 256
#define HW 16384
#define LBLK 1024
#define NLBLK 128
#define ROW_TILES 15
#define COL_CHUNKS 20
#define NSUB 343
#define TEMP_INV 10.0f
#define L2E10 14.426950408889634f
#define LOSS_SCALE 1.4285714285714286f

// -------------------- device scratch --------------------
__device__ int g_lab64;
__device__ int g_bcnt[NLBLK * NUM_CLASSES];
__device__ int g_boff[NLBLK * NUM_CLASSES];
__device__ int g_idx[NA];
__device__ __align__(16) __nv_bfloat16 g_A[NA_PAD * DIMS];
__device__ __align__(16) __nv_bfloat16 g_C[NC_PAD * DIMS];
__device__ int g_clab[NC_PAD];
__device__ float g_Sp[NA_PAD * COL_CHUNKS];
__device__ float g_Pp[NA_PAD * COL_CHUNKS];

__device__ __forceinline__ int load_label(const void* p, int i) {
    if (g_lab64) return (int)((const long long*)p)[i];
    return ((const int*)p)[i];
}

// fused exp-and-accumulate: S += exp(10*acc), P += acc if labels match.
__device__ __forceinline__ void ep_core(float acc_v, int labv, int rl, float& S, float& P) {
    float zf = fmaf(acc_v, L2E10, 12582912.0f);
    int   zi = __float_as_int(zf);
    float n  = zf - 12582912.0f;
    float f  = fmaf(acc_v, L2E10, -n);
    float p  = 1.5403530393381609e-4f;
    p = fmaf(p, f, 1.3333558146428443e-3f);
    p = fmaf(p, f, 9.6181291076284772e-3f);
    p = fmaf(p, f, 5.5504108664821580e-2f);
    p = fmaf(p, f, 2.4022650695910071e-1f);
    p = fmaf(p, f, 6.9314718055994531e-1f);
    p = fmaf(p, f, 1.0f);
    float sc = __int_as_float((zi << 23) + 0x3F800000);
    S = fmaf(p, sc, S);
    if (labv == rl) P += acc_v;
}

__device__ __forceinline__ void mma_bf16(float* d, const unsigned* a, const unsigned* b) {
    asm volatile(
        "mma.sync.aligned.m16n8k16.row.col.f32.bf16.bf16.f32 "
        "{%0,%1,%2,%3}, {%4,%5,%6,%7}, {%8,%9}, {%0,%1,%2,%3};\n"
        : "+f"(d[0]), "+f"(d[1]), "+f"(d[2]), "+f"(d[3])
        : "r"(a[0]), "r"(a[1]), "r"(a[2]), "r"(a[3]), "r"(b[0]), "r"(b[1]));
}

// -------------------- label dtype detection --------------------
__global__ void k_detect(const int* lab32) {
    int lane = threadIdx.x;
    int bad = 0;
    #pragma unroll 4
    for (int i = lane; i < 1024; i += 32) bad |= lab32[2 * i + 1];
    unsigned m = __ballot_sync(0xffffffffu, bad != 0);
    if (lane == 0) g_lab64 = (m == 0) ? 1 : 0;
}

// -------------------- sampling --------------------
__global__ void k_count(const void* labels) {
    __shared__ int scnt[NUM_CLASSES];
    int t = threadIdx.x;
    if (t < NUM_CLASSES) scnt[t] = 0;
    __syncthreads();
    int base = blockIdx.x * LBLK;
    for (int i = t; i < LBLK; i += 256) {
        int c = load_label(labels, base + i);
        atomicAdd(&scnt[c], 1);
    }
    __syncthreads();
    if (t < NUM_CLASSES) g_bcnt[blockIdx.x * NUM_CLASSES + t] = scnt[t];
}

__global__ void k_scan() {
    int c = threadIdx.x;
    if (c >= NUM_CLASSES) return;
    int run = 0;
    for (int b = 0; b < NLBLK; b++) {
        g_boff[b * NUM_CLASSES + c] = run;
        run += g_bcnt[b * NUM_CLASSES + c];
    }
}

// one warp per class, warp-ballot ranking; 19 warps = 608 threads per block
__global__ void k_select(const void* labels) {
    int w    = threadIdx.x >> 5;        // class
    int lane = threadIdx.x & 31;
    int b    = blockIdx.x;
    int r = g_boff[b * NUM_CLASSES + w];
    if (r >= KPC) return;               // uniform per warp
    int base = b * LBLK;
    // prefetch this lane's 32 labels (MLP=32, one latency)
    int myl[32];
    #pragma unroll
    for (int s = 0; s < 32; s++)
        myl[s] = load_label(labels, base + s * 32 + lane);
    unsigned below = (1u << lane) - 1u;
    #pragma unroll 8
    for (int s = 0; s < 32; s++) {
        unsigned m = __ballot_sync(0xffffffffu, myl[s] == w);
        if (myl[s] == w) {
            int rank = r + __popc(m & below);
            if (rank < KPC) g_idx[w * KPC + rank] = base + s * 32 + lane;
        }
        r += __popc(m);
        if (r >= KPC) break;            // uniform
    }
}

// -------------------- gather + normalize anchors --------------------
__global__ void k_anchor(const float* __restrict__ pf) {
    int wid  = threadIdx.x >> 5;
    int lane = threadIdx.x & 31;
    int n = blockIdx.x * 8 + wid;
    float v[8];
    if (n < NA) {
        int idx = g_idx[n];
        int b   = idx >> 14;
        int rem = idx & (HW - 1);
        const float* src = pf + (size_t)b * (DIMS * HW) + rem;
        #pragma unroll
        for (int j = 0; j < 8; j++)
            v[j] = src[(size_t)(lane + 32 * j) * HW];
    } else {
        #pragma unroll
        for (int j = 0; j < 8; j++) v[j] = 0.f;
    }
    float ss = 0.f;
    #pragma unroll
    for (int j = 0; j < 8; j++) ss += v[j] * v[j];
    #pragma unroll
    for (int o = 16; o; o >>= 1) ss += __shfl_xor_sync(0xffffffffu, ss, o);
    float sc = (n < NA) ? (1.f / fmaxf(sqrtf(ss), 1e-12f)) : 0.f;
    #pragma unroll
    for (int j = 0; j < 8; j++) {
        __nv_bfloat16 o16 = __float2bfloat16(v[j] * sc);
        int d = lane + 32 * j;
        g_A[n * DIMS + d] = o16;
        g_C[n * DIMS + d] = o16;
    }
}

// -------------------- normalize memory feats --------------------
__global__ void k_mem(const float* __restrict__ mf) {
    int wid  = threadIdx.x >> 5;
    int lane = threadIdx.x & 31;
    int m = blockIdx.x * 8 + wid;
    if (m >= NC_PAD - NA) return;
    float v[8];
    if (m < NMEM) {
        const float* src = mf + (size_t)m * DIMS;
        #pragma unroll
        for (int j = 0; j < 8; j++) v[j] = src[lane + 32 * j];
    } else {
        #pragma unroll
        for (int j = 0; j < 8; j++) v[j] = 0.f;
    }
    float ss = 0.f;
    #pragma unroll
    for (int j = 0; j < 8; j++) ss += v[j] * v[j];
    #pragma unroll
    for (int o = 16; o; o >>= 1) ss += __shfl_xor_sync(0xffffffffu, ss, o);
    float sc = (m < NMEM) ? (1.f / fmaxf(sqrtf(ss), 1e-12f)) : 0.f;
    #pragma unroll
    for (int j = 0; j < 8; j++)
        g_C[(size_t)(NA + m) * DIMS + lane + 32 * j] = __float2bfloat16(v[j] * sc);
}

__global__ void k_label(const void* mlab) {
    int i = blockIdx.x * 256 + threadIdx.x;
    if (i >= NC_PAD) return;
    int v;
    if (i < NA)         v = i / KPC;
    else if (i < NCOLS) v = load_label(mlab, i - NA);
    else                v = -1;
    g_clab[i] = v;
}

// -------------------- fused GEMM + softmax reductions --------------------
extern __shared__ char smem_raw[];

#define AS_BYTES (128 * 264 * 2)
#define CS_BYTES (64 * 264 * 2)
#define SMEM_BYTES (AS_BYTES + CS_BYTES + 64 * 4 + 2 * 256 * 4)

__global__ void __launch_bounds__(256) k_main() {
    __nv_bfloat16* As = (__nv_bfloat16*)smem_raw;                        // [128][264]
    __nv_bfloat16* Cs = (__nv_bfloat16*)(smem_raw + AS_BYTES);           // [64][264]
    int*   clab_sm = (int*)(smem_raw + AS_BYTES + CS_BYTES);             // [64]
    float* redS    = (float*)(smem_raw + AS_BYTES + CS_BYTES + 64 * 4);  // [128][2]
    float* redP    = redS + 256;

    const int tid     = threadIdx.x;
    const int chunk   = blockIdx.x;
    const int rowbase = blockIdx.y * 128;
    const int lane = tid & 31;
    const int w    = tid >> 5;
    const int wr   = w >> 1;
    const int wc   = w & 1;
    const int g    = lane >> 2;
    const int t2   = (lane & 3) * 2;

    const int ld_row = tid >> 5;     // this thread's Cs row (0..7 offsets of 8)
    const int ld_kv  = tid & 31;     // uint4 chunk within row

    // A tile [128][256]
    #pragma unroll
    for (int it = 0; it < 16; it++) {
        int lin = tid + it * 256;
        int row = lin >> 5;
        int kv  = lin & 31;
        *(uint4*)(As + row * 264 + kv * 8) =
            *(const uint4*)(g_A + (size_t)(rowbase + row) * DIMS + kv * 8);
    }

    float Sacc[2][2] = {{0.f, 0.f}, {0.f, 0.f}};
    float Pacc[2][2] = {{0.f, 0.f}, {0.f, 0.f}};
    int rlab[2][2], grow[2][2];
    #pragma unroll
    for (int mb = 0; mb < 2; mb++)
        #pragma unroll
        for (int p = 0; p < 2; p++) {
            int r = rowbase + wr * 32 + mb * 16 + g + 8 * p;
            grow[mb][p] = r;
            rlab[mb][p] = (r < NA) ? (r / KPC) : -2;
        }

    // prefetch first subtile into registers
    uint4 pre[8];
    int   prelab = 0;
    {
        const int colbase = chunk * 64;
        #pragma unroll
        for (int it = 0; it < 8; it++)
            pre[it] = *(const uint4*)(g_C + (size_t)(colbase + ld_row + it * 8) * DIMS + ld_kv * 8);
        if (tid < 64) prelab = g_clab[colbase + tid];
    }

    for (int s = chunk; s < NSUB; s += COL_CHUNKS) {
        const int colbase = s * 64;
        const bool edge = (colbase + 64 > NCOLS) ||
                          ((colbase < rowbase + 128) && (colbase + 64 > rowbase));
        __syncthreads();
        #pragma unroll
        for (int it = 0; it < 8; it++)
            *(uint4*)(Cs + (ld_row + it * 8) * 264 + ld_kv * 8) = pre[it];
        if (tid < 64) clab_sm[tid] = prelab;
        __syncthreads();

        // prefetch next subtile while computing this one
        const int ns = s + COL_CHUNKS;
        if (ns < NSUB) {
            const int ncb = ns * 64;
            #pragma unroll
            for (int it = 0; it < 8; it++)
                pre[it] = *(const uint4*)(g_C + (size_t)(ncb + ld_row + it * 8) * DIMS + ld_kv * 8);
            if (tid < 64) prelab = g_clab[ncb + tid];
        }

        float acc[2][4][4];
        #pragma unroll
        for (int mb = 0; mb < 2; mb++)
            #pragma unroll
            for (int nb = 0; nb < 4; nb++)
                #pragma unroll
                for (int i = 0; i < 4; i++) acc[mb][nb][i] = 0.f;

        #pragma unroll
        for (int k = 0; k < DIMS; k += 16) {
            unsigned a[2][4], b[4][2];
            #pragma unroll
            for (int mb = 0; mb < 2; mb++) {
                const __nv_bfloat16* a0 = As + (wr * 32 + mb * 16 + g) * 264 + k + t2;
                a[mb][0] = *(const unsigned*)(a0);
                a[mb][1] = *(const unsigned*)(a0 + 8 * 264);
                a[mb][2] = *(const unsigned*)(a0 + 8);
                a[mb][3] = *(const unsigned*)(a0 + 8 * 264 + 8);
            }
            #pragma unroll
            for (int nb = 0; nb < 4; nb++) {
                const __nv_bfloat16* cb = Cs + (wc * 32 + nb * 8 + g) * 264 + k + t2;
                b[nb][0] = *(const unsigned*)(cb);
                b[nb][1] = *(const unsigned*)(cb + 8);
            }
            #pragma unroll
            for (int mb = 0; mb < 2; mb++)
                #pragma unroll
                for (int nb = 0; nb < 4; nb++)
                    mma_bf16(acc[mb][nb], a[mb], b[nb]);
        }

        int labreg[8];
        #pragma unroll
        for (int nb = 0; nb < 4; nb++)
            #pragma unroll
            for (int e = 0; e < 2; e++)
                labreg[nb * 2 + e] = clab_sm[wc * 32 + nb * 8 + t2 + e];

        if (!edge) {
            #pragma unroll
            for (int mb = 0; mb < 2; mb++)
                #pragma unroll
                for (int nb = 0; nb < 4; nb++)
                    #pragma unroll
                    for (int p = 0; p < 2; p++)
                        #pragma unroll
                        for (int e = 0; e < 2; e++)
                            ep_core(acc[mb][nb][2 * p + e], labreg[nb * 2 + e],
                                    rlab[mb][p], Sacc[mb][p], Pacc[mb][p]);
        } else {
            #pragma unroll
            for (int mb = 0; mb < 2; mb++)
                #pragma unroll
                for (int nb = 0; nb < 4; nb++) {
                    int colb = wc * 32 + nb * 8 + t2;
                    #pragma unroll
                    for (int p = 0; p < 2; p++)
                        #pragma unroll
                        for (int e = 0; e < 2; e++) {
                            int gcol = colbase + colb + e;
                            if (gcol < NCOLS && gcol != grow[mb][p])
                                ep_core(acc[mb][nb][2 * p + e], labreg[nb * 2 + e],
                                        rlab[mb][p], Sacc[mb][p], Pacc[mb][p]);
                        }
                }
        }
    }

    #pragma unroll
    for (int mb = 0; mb < 2; mb++)
        #pragma unroll
        for (int p = 0; p < 2; p++) {
            float sv = Sacc[mb][p], pv = Pacc[mb][p];
            sv += __shfl_xor_sync(0xffffffffu, sv, 1);
            sv += __shfl_xor_sync(0xffffffffu, sv, 2);
            pv += __shfl_xor_sync(0xffffffffu, pv, 1);
            pv += __shfl_xor_sync(0xffffffffu, pv, 2);
            if ((lane & 3) == 0) {
                int row = wr * 32 + mb * 16 + g + 8 * p;
                redS[row * 2 + wc] = sv;
                redP[row * 2 + wc] = pv;
            }
        }
    __syncthreads();
    if (tid < 128) {
        int r = rowbase + tid;
        g_Sp[r * COL_CHUNKS + chunk] = redS[tid * 2] + redS[tid * 2 + 1];
        g_Pp[r * COL_CHUNKS + chunk] = redP[tid * 2] + redP[tid * 2 + 1];
    }
}

// -------------------- final scalar reduction --------------------
__global__ void k_final(const void* mlab, float* out) {
    __shared__ int scnt[NUM_CLASSES];
    __shared__ float ssum[256];
    int t = threadIdx.x;
    if (t < NUM_CLASSES) scnt[t] = 0;
    __syncthreads();
    for (int i = t; i < NMEM; i += 256)
        atomicAdd(&scnt[load_label(mlab, i)], 1);
    __syncthreads();
    float local = 0.f;
    for (int n = t; n < NA; n += 256) {
        float S = 0.f, P = 0.f;
        #pragma unroll
        for (int ch = 0; ch < COL_CHUNKS; ch++) {
            S += g_Sp[n * COL_CHUNKS + ch];
            P += g_Pp[n * COL_CHUNKS + ch];
        }
        float cnt = (float)(KPC - 1 + scnt[n / KPC]);
        local += (TEMP_INV * P - cnt * logf(S + 1e-12f)) / cnt;
    }
    ssum[t] = local;
    __syncthreads();
    for (int off = 128; off; off >>= 1) {
        if (t < off) ssum[t] += ssum[t + off];
        __syncthreads();
    }
    if (t == 0) out[0] = -LOSS_SCALE * ssum[0] / (float)NA;
}

// -------------------- launch --------------------
extern "C" void kernel_launch(void* const* d_in, const int* in_sizes, int n_in,
                              void* d_out, int out_size) {
    (void)in_sizes; (void)n_in; (void)out_size;
    const float* pf   = (const float*)d_in[0];
    const void*  lab  = d_in[1];
    const float* mf   = (const float*)d_in[2];
    const void*  mlab = d_in[3];
    float* out = (float*)d_out;

    cudaFuncSetAttribute(k_main, cudaFuncAttributeMaxDynamicSharedMemorySize, SMEM_BYTES);

    k_detect<<<1, 32>>>((const int*)lab);
    k_count<<<NLBLK, 256>>>(lab);
    k_scan<<<1, 32>>>();
    k_select<<<NLBLK, NUM_CLASSES * 32>>>(lab);
    k_anchor<<<NA_PAD / 8, 256>>>(pf);
    k_mem<<<(NC_PAD - NA + 7) / 8, 256>>>(mf);
    k_label<<<(NC_PAD + 255) / 256, 256>>>(mlab);
    k_main<<<dim3(COL_CHUNKS, ROW_TILES), 256, SMEM_BYTES>>>();
    k_final<<<1, 256>>>(mlab, out);
}

// round 5
// speedup vs baseline: 1.4801x; 1.1046x over previous
#include <cuda_runtime.h>
#include <cuda_bf16.h>
#include <math.h>

#define NUM_CLASSES 19
#define KPC 100
#define NA 1900
#define NA_PAD 1920
#define NMEM 20000
#define NCOLS 21900
#define NC_PAD 21952
#define DIMS 256
#define HW 16384
#define LBLK 1024
#define NLBLK 128
#define ROW_TILES 15
#define COL_CHUNKS 20
#define NSUB 343
#define TEMP_INV 10.0f
#define L2E10 14.426950408889634f
#define LOSS_SCALE 1.4285714285714286f

// -------------------- device scratch --------------------
__device__ int g_lab64;
__device__ int g_bcnt[NLBLK * NUM_CLASSES];
__device__ int g_boff[NLBLK * NUM_CLASSES];
__device__ int g_idx[NA];
__device__ __align__(16) __nv_bfloat16 g_A[NA_PAD * DIMS];
__device__ __align__(16) __nv_bfloat16 g_C[NC_PAD * DIMS];
__device__ int g_clab[NC_PAD];
__device__ float g_Sp[NA_PAD * COL_CHUNKS];
__device__ float g_Pp[NA_PAD * COL_CHUNKS];

__device__ __forceinline__ int load_label(const void* p, int i) {
    if (g_lab64) return (int)((const long long*)p)[i];
    return ((const int*)p)[i];
}

// fused exp-and-accumulate: S += exp(10*acc), P += acc if labels match.
// degree-5 2^f poly on [-0.5,0.5], FMA pipe only.
__device__ __forceinline__ void ep_core(float acc_v, int labv, int rl, float& S, float& P) {
    float zf = fmaf(acc_v, L2E10, 12582912.0f);
    int   zi = __float_as_int(zf);
    float n  = zf - 12582912.0f;
    float f  = fmaf(acc_v, L2E10, -n);
    float p  = 1.3333558146428443e-3f;
    p = fmaf(p, f, 9.6181291076284772e-3f);
    p = fmaf(p, f, 5.5504108664821580e-2f);
    p = fmaf(p, f, 2.4022650695910071e-1f);
    p = fmaf(p, f, 6.9314718055994531e-1f);
    p = fmaf(p, f, 1.0f);
    float sc = __int_as_float((zi << 23) + 0x3F800000);
    S = fmaf(p, sc, S);
    if (labv == rl) P += acc_v;
}

__device__ __forceinline__ void mma_bf16(float* d, const unsigned* a, const unsigned* b) {
    asm volatile(
        "mma.sync.aligned.m16n8k16.row.col.f32.bf16.bf16.f32 "
        "{%0,%1,%2,%3}, {%4,%5,%6,%7}, {%8,%9}, {%0,%1,%2,%3};\n"
        : "+f"(d[0]), "+f"(d[1]), "+f"(d[2]), "+f"(d[3])
        : "r"(a[0]), "r"(a[1]), "r"(a[2]), "r"(a[3]), "r"(b[0]), "r"(b[1]));
}

__device__ __forceinline__ void ldsm_x4(unsigned& r0, unsigned& r1, unsigned& r2,
                                        unsigned& r3, unsigned addr) {
    asm volatile("ldmatrix.sync.aligned.m8n8.x4.shared.b16 {%0,%1,%2,%3}, [%4];"
                 : "=r"(r0), "=r"(r1), "=r"(r2), "=r"(r3) : "r"(addr));
}

// -------------------- label dtype detection --------------------
__global__ void k_detect(const int* lab32) {
    int lane = threadIdx.x;
    int bad = 0;
    #pragma unroll 4
    for (int i = lane; i < 1024; i += 32) bad |= lab32[2 * i + 1];
    unsigned m = __ballot_sync(0xffffffffu, bad != 0);
    if (lane == 0) g_lab64 = (m == 0) ? 1 : 0;
}

// -------------------- sampling --------------------
__global__ void k_count(const void* labels) {
    __shared__ int scnt[NUM_CLASSES];
    int t = threadIdx.x;
    if (t < NUM_CLASSES) scnt[t] = 0;
    __syncthreads();
    int base = blockIdx.x * LBLK;
    for (int i = t; i < LBLK; i += 256) {
        int c = load_label(labels, base + i);
        atomicAdd(&scnt[c], 1);
    }
    __syncthreads();
    if (t < NUM_CLASSES) g_bcnt[blockIdx.x * NUM_CLASSES + t] = scnt[t];
}

__global__ void k_scan() {
    int c = threadIdx.x;
    if (c >= NUM_CLASSES) return;
    int run = 0;
    for (int b = 0; b < NLBLK; b++) {
        g_boff[b * NUM_CLASSES + c] = run;
        run += g_bcnt[b * NUM_CLASSES + c];
    }
}

// one warp per class, warp-ballot ranking
__global__ void k_select(const void* labels) {
    int w    = threadIdx.x >> 5;
    int lane = threadIdx.x & 31;
    int b    = blockIdx.x;
    int r = g_boff[b * NUM_CLASSES + w];
    if (r >= KPC) return;
    int base = b * LBLK;
    int myl[32];
    #pragma unroll
    for (int s = 0; s < 32; s++)
        myl[s] = load_label(labels, base + s * 32 + lane);
    unsigned below = (1u << lane) - 1u;
    #pragma unroll 8
    for (int s = 0; s < 32; s++) {
        unsigned m = __ballot_sync(0xffffffffu, myl[s] == w);
        if (myl[s] == w) {
            int rank = r + __popc(m & below);
            if (rank < KPC) g_idx[w * KPC + rank] = base + s * 32 + lane;
        }
        r += __popc(m);
        if (r >= KPC) break;
    }
}

// -------------------- gather + normalize anchors --------------------
__global__ void k_anchor(const float* __restrict__ pf) {
    int wid  = threadIdx.x >> 5;
    int lane = threadIdx.x & 31;
    int n = blockIdx.x * 8 + wid;
    float v[8];
    if (n < NA) {
        int idx = g_idx[n];
        int b   = idx >> 14;
        int rem = idx & (HW - 1);
        const float* src = pf + (size_t)b * (DIMS * HW) + rem;
        #pragma unroll
        for (int j = 0; j < 8; j++)
            v[j] = src[(size_t)(lane + 32 * j) * HW];
    } else {
        #pragma unroll
        for (int j = 0; j < 8; j++) v[j] = 0.f;
    }
    float ss = 0.f;
    #pragma unroll
    for (int j = 0; j < 8; j++) ss += v[j] * v[j];
    #pragma unroll
    for (int o = 16; o; o >>= 1) ss += __shfl_xor_sync(0xffffffffu, ss, o);
    float sc = (n < NA) ? (1.f / fmaxf(sqrtf(ss), 1e-12f)) : 0.f;
    #pragma unroll
    for (int j = 0; j < 8; j++) {
        __nv_bfloat16 o16 = __float2bfloat16(v[j] * sc);
        int d = lane + 32 * j;
        g_A[n * DIMS + d] = o16;
        g_C[n * DIMS + d] = o16;
    }
}

// -------------------- normalize memory feats --------------------
__global__ void k_mem(const float* __restrict__ mf) {
    int wid  = threadIdx.x >> 5;
    int lane = threadIdx.x & 31;
    int m = blockIdx.x * 8 + wid;
    if (m >= NC_PAD - NA) return;
    float v[8];
    if (m < NMEM) {
        const float* src = mf + (size_t)m * DIMS;
        #pragma unroll
        for (int j = 0; j < 8; j++) v[j] = src[lane + 32 * j];
    } else {
        #pragma unroll
        for (int j = 0; j < 8; j++) v[j] = 0.f;
    }
    float ss = 0.f;
    #pragma unroll
    for (int j = 0; j < 8; j++) ss += v[j] * v[j];
    #pragma unroll
    for (int o = 16; o; o >>= 1) ss += __shfl_xor_sync(0xffffffffu, ss, o);
    float sc = (m < NMEM) ? (1.f / fmaxf(sqrtf(ss), 1e-12f)) : 0.f;
    #pragma unroll
    for (int j = 0; j < 8; j++)
        g_C[(size_t)(NA + m) * DIMS + lane + 32 * j] = __float2bfloat16(v[j] * sc);
}

__global__ void k_label(const void* mlab) {
    int i = blockIdx.x * 256 + threadIdx.x;
    if (i >= NC_PAD) return;
    int v;
    if (i < NA)         v = i / KPC;
    else if (i < NCOLS) v = load_label(mlab, i - NA);
    else                v = -1;
    g_clab[i] = v;
}

// -------------------- fused GEMM + softmax reductions --------------------
extern __shared__ char smem_raw[];

#define AS_BYTES (128 * 264 * 2)
#define CS_BYTES (64 * 264 * 2)
#define SMEM_BYTES (AS_BYTES + CS_BYTES + 64 * 4 + 2 * 256 * 4)

__global__ void __launch_bounds__(256) k_main() {
    __nv_bfloat16* As = (__nv_bfloat16*)smem_raw;                        // [128][264]
    __nv_bfloat16* Cs = (__nv_bfloat16*)(smem_raw + AS_BYTES);           // [64][264]
    int*   clab_sm = (int*)(smem_raw + AS_BYTES + CS_BYTES);             // [64]
    float* redS    = (float*)(smem_raw + AS_BYTES + CS_BYTES + 64 * 4);  // [128][2]
    float* redP    = redS + 256;

    const int tid     = threadIdx.x;
    const int chunk   = blockIdx.x;
    const int rowbase = blockIdx.y * 128;
    const int lane = tid & 31;
    const int w    = tid >> 5;
    const int wr   = w >> 1;
    const int wc   = w & 1;
    const int g    = lane >> 2;
    const int t2   = (lane & 3) * 2;

    const int ld_row = tid >> 5;
    const int ld_kv  = tid & 31;

    // A tile [128][256]
    #pragma unroll
    for (int it = 0; it < 16; it++) {
        int lin = tid + it * 256;
        int row = lin >> 5;
        int kv  = lin & 31;
        *(uint4*)(As + row * 264 + kv * 8) =
            *(const uint4*)(g_A + (size_t)(rowbase + row) * DIMS + kv * 8);
    }

    // ldmatrix lane addresses (byte offsets in shared space)
    unsigned as_u32 = (unsigned)__cvta_generic_to_shared(As);
    unsigned cs_u32 = (unsigned)__cvta_generic_to_shared(Cs);
    unsigned aAddr[2], bAddr[2];
    {
        int arow = (lane & 7) + ((lane >> 3) & 1) * 8;   // row within 16-row tile
        int acol = (lane >> 4) * 8;                      // 0 or 8
        #pragma unroll
        for (int mb = 0; mb < 2; mb++)
            aAddr[mb] = as_u32 + ((wr * 32 + mb * 16 + arow) * 264 + acol) * 2;
        int brow = ((lane >> 4) & 1) * 8 + (lane & 7);   // row within 16-row (two nb) tile
        int bcol = ((lane >> 3) & 1) * 8;
        #pragma unroll
        for (int pr = 0; pr < 2; pr++)
            bAddr[pr] = cs_u32 + ((wc * 32 + pr * 16 + brow) * 264 + bcol) * 2;
    }

    float Sacc[2][2] = {{0.f, 0.f}, {0.f, 0.f}};
    float Pacc[2][2] = {{0.f, 0.f}, {0.f, 0.f}};
    int rlab[2][2], grow[2][2];
    #pragma unroll
    for (int mb = 0; mb < 2; mb++)
        #pragma unroll
        for (int p = 0; p < 2; p++) {
            int r = rowbase + wr * 32 + mb * 16 + g + 8 * p;
            grow[mb][p] = r;
            rlab[mb][p] = (r < NA) ? (r / KPC) : -2;
        }

    // prefetch first subtile into registers
    uint4 pre[8];
    int   prelab = 0;
    {
        const int colbase = chunk * 64;
        #pragma unroll
        for (int it = 0; it < 8; it++)
            pre[it] = *(const uint4*)(g_C + (size_t)(colbase + ld_row + it * 8) * DIMS + ld_kv * 8);
        if (tid < 64) prelab = g_clab[colbase + tid];
    }

    for (int s = chunk; s < NSUB; s += COL_CHUNKS) {
        const int colbase = s * 64;
        const bool edge = (colbase + 64 > NCOLS) ||
                          ((colbase < rowbase + 128) && (colbase + 64 > rowbase));
        __syncthreads();
        #pragma unroll
        for (int it = 0; it < 8; it++)
            *(uint4*)(Cs + (ld_row + it * 8) * 264 + ld_kv * 8) = pre[it];
        if (tid < 64) clab_sm[tid] = prelab;
        __syncthreads();

        const int ns = s + COL_CHUNKS;
        if (ns < NSUB) {
            const int ncb = ns * 64;
            #pragma unroll
            for (int it = 0; it < 8; it++)
                pre[it] = *(const uint4*)(g_C + (size_t)(ncb + ld_row + it * 8) * DIMS + ld_kv * 8);
            if (tid < 64) prelab = g_clab[ncb + tid];
        }

        float acc[2][4][4];
        #pragma unroll
        for (int mb = 0; mb < 2; mb++)
            #pragma unroll
            for (int nb = 0; nb < 4; nb++)
                #pragma unroll
                for (int i = 0; i < 4; i++) acc[mb][nb][i] = 0.f;

        #pragma unroll
        for (int k = 0; k < DIMS; k += 16) {
            unsigned a[2][4], b[4][2];
            #pragma unroll
            for (int mb = 0; mb < 2; mb++)
                ldsm_x4(a[mb][0], a[mb][1], a[mb][2], a[mb][3], aAddr[mb] + k * 2);
            #pragma unroll
            for (int pr = 0; pr < 2; pr++)
                ldsm_x4(b[2 * pr][0], b[2 * pr][1], b[2 * pr + 1][0], b[2 * pr + 1][1],
                        bAddr[pr] + k * 2);
            #pragma unroll
            for (int mb = 0; mb < 2; mb++)
                #pragma unroll
                for (int nb = 0; nb < 4; nb++)
                    mma_bf16(acc[mb][nb], a[mb], b[nb]);
        }

        int labreg[8];
        #pragma unroll
        for (int nb = 0; nb < 4; nb++)
            #pragma unroll
            for (int e = 0; e < 2; e++)
                labreg[nb * 2 + e] = clab_sm[wc * 32 + nb * 8 + t2 + e];

        if (!edge) {
            #pragma unroll
            for (int mb = 0; mb < 2; mb++)
                #pragma unroll
                for (int nb = 0; nb < 4; nb++)
                    #pragma unroll
                    for (int p = 0; p < 2; p++)
                        #pragma unroll
                        for (int e = 0; e < 2; e++)
                            ep_core(acc[mb][nb][2 * p + e], labreg[nb * 2 + e],
                                    rlab[mb][p], Sacc[mb][p], Pacc[mb][p]);
        } else {
            #pragma unroll
            for (int mb = 0; mb < 2; mb++)
                #pragma unroll
                for (int nb = 0; nb < 4; nb++) {
                    int colb = wc * 32 + nb * 8 + t2;
                    #pragma unroll
                    for (int p = 0; p < 2; p++)
                        #pragma unroll
                        for (int e = 0; e < 2; e++) {
                            int gcol = colbase + colb + e;
                            if (gcol < NCOLS && gcol != grow[mb][p])
                                ep_core(acc[mb][nb][2 * p + e], labreg[nb * 2 + e],
                                        rlab[mb][p], Sacc[mb][p], Pacc[mb][p]);
                        }
                }
        }
    }

    #pragma unroll
    for (int mb = 0; mb < 2; mb++)
        #pragma unroll
        for (int p = 0; p < 2; p++) {
            float sv = Sacc[mb][p], pv = Pacc[mb][p];
            sv += __shfl_xor_sync(0xffffffffu, sv, 1);
            sv += __shfl_xor_sync(0xffffffffu, sv, 2);
            pv += __shfl_xor_sync(0xffffffffu, pv, 1);
            pv += __shfl_xor_sync(0xffffffffu, pv, 2);
            if ((lane & 3) == 0) {
                int row = wr * 32 + mb * 16 + g + 8 * p;
                redS[row * 2 + wc] = sv;
                redP[row * 2 + wc] = pv;
            }
        }
    __syncthreads();
    if (tid < 128) {
        int r = rowbase + tid;
        g_Sp[r * COL_CHUNKS + chunk] = redS[tid * 2] + redS[tid * 2 + 1];
        g_Pp[r * COL_CHUNKS + chunk] = redP[tid * 2] + redP[tid * 2 + 1];
    }
}

// -------------------- final scalar reduction (1024 threads) --------------------
__global__ void k_final(const void* mlab, float* out) {
    __shared__ int scnt[NUM_CLASSES];
    __shared__ float wsum[32];
    int t = threadIdx.x;
    int lane = t & 31, wid = t >> 5;
    if (t < NUM_CLASSES) scnt[t] = 0;
    __syncthreads();
    for (int i = t; i < NMEM; i += 1024)
        atomicAdd(&scnt[load_label(mlab, i)], 1);
    __syncthreads();
    float local = 0.f;
    for (int n = t; n < NA; n += 1024) {
        float S = 0.f, P = 0.f;
        #pragma unroll
        for (int ch = 0; ch < COL_CHUNKS; ch++) {
            S += g_Sp[n * COL_CHUNKS + ch];
            P += g_Pp[n * COL_CHUNKS + ch];
        }
        float cnt = (float)(KPC - 1 + scnt[n / KPC]);
        local += (TEMP_INV * P - cnt * logf(S + 1e-12f)) / cnt;
    }
    #pragma unroll
    for (int o = 16; o; o >>= 1) local += __shfl_xor_sync(0xffffffffu, local, o);
    if (lane == 0) wsum[wid] = local;
    __syncthreads();
    if (t < 32) {
        float v = wsum[t];
        #pragma unroll
        for (int o = 16; o; o >>= 1) v += __shfl_xor_sync(0xffffffffu, v, o);
        if (t == 0) out[0] = -LOSS_SCALE * v / (float)NA;
    }
}

// -------------------- launch --------------------
extern "C" void kernel_launch(void* const* d_in, const int* in_sizes, int n_in,
                              void* d_out, int out_size) {
    (void)in_sizes; (void)n_in; (void)out_size;
    const float* pf   = (const float*)d_in[0];
    const void*  lab  = d_in[1];
    const float* mf   = (const float*)d_in[2];
    const void*  mlab = d_in[3];
    float* out = (float*)d_out;

    cudaFuncSetAttribute(k_main, cudaFuncAttributeMaxDynamicSharedMemorySize, SMEM_BYTES);

    k_detect<<<1, 32>>>((const int*)lab);
    k_count<<<NLBLK, 256>>>(lab);
    k_scan<<<1, 32>>>();
    k_select<<<NLBLK, NUM_CLASSES * 32>>>(lab);
    k_anchor<<<NA_PAD / 8, 256>>>(pf);
    k_mem<<<(NC_PAD - NA + 7) / 8, 256>>>(mf);
    k_label<<<(NC_PAD + 255) / 256, 256>>>(mlab);
    k_main<<<dim3(COL_CHUNKS, ROW_TILES), 256, SMEM_BYTES>>>();
    k_final<<<1, 1024>>>(mlab, out);
}